// round 12
// baseline (speedup 1.0000x reference)
#include <cuda_runtime.h>
#include <cuda_bf16.h>

// Damping_27066883900008 R12: cross-pair software pipeline. 4 pairs/thread;
// the FMA-heavy mainloop of pair i+1 is fused k-by-k with the MUFU-heavy
// layer-3 of pair i, so both pipes are fed evenly (35 FFMA2 + 4 tanh2 per
// fused iter) instead of phase-aligned bursts. block=128 x 3 CTAs.

#define NT 128
#define ITERS 4
typedef unsigned long long ull;

struct __align__(16) Params {
    ull   w2p[256];    // (16,16) packed {wd2, wo2}, 16B-aligned pairs
    ull   w1p[32];     // (2,16)  packed {wd1, wo1}
    ull   b1p[16];     // {bd1, bo1}
    ull   b2p[16];     // {bd2, bo2}
    ull   wd3ap[16];   // {wd3[k][0], wd3[k][0]}
    ull   wd3bp[16];   // {wd3[k][1], wd3[k][1]}
    ull   wo3p[16];    // {wo3[k],    wo3[k]}
    ull   bd30p, bd31p, bo3p;
};

__device__    Params g_pack;
__constant__  Params c_p;

__device__ __forceinline__ ull pack2(float lo, float hi) {
    ull r; asm("mov.b64 %0, {%1, %2};" : "=l"(r) : "f"(lo), "f"(hi)); return r;
}
__device__ __forceinline__ void unpack2(ull v, float& lo, float& hi) {
    asm("mov.b64 {%0, %1}, %2;" : "=f"(lo), "=f"(hi) : "l"(v));
}
__device__ __forceinline__ ull fma2(ull a, ull b, ull c) {
    ull d; asm("fma.rn.f32x2 %0, %1, %2, %3;" : "=l"(d) : "l"(a), "l"(b), "l"(c)); return d;
}
__device__ __forceinline__ ull mul2(ull a, ull b) {
    ull d; asm("mul.rn.f32x2 %0, %1, %2;" : "=l"(d) : "l"(a), "l"(b)); return d;
}
__device__ __forceinline__ ull add2(ull a, ull b) {
    ull d; asm("add.rn.f32x2 %0, %1, %2;" : "=l"(d) : "l"(a), "l"(b)); return d;
}
__device__ __forceinline__ float tanh_ap(float x) {
    float y; asm("tanh.approx.f32 %0, %1;" : "=f"(y) : "f"(x)); return y;
}
__device__ __forceinline__ ull tanh2(ull v) {
    float lo, hi; unpack2(v, lo, hi);
    return pack2(tanh_ap(lo), tanh_ap(hi));
}

__global__ void pack_kernel(
    const float* __restrict__ w_d1, const float* __restrict__ w_d2,
    const float* __restrict__ w_d3, const float* __restrict__ w_o1,
    const float* __restrict__ w_o2, const float* __restrict__ w_o3,
    const float* __restrict__ b_d1, const float* __restrict__ b_d2,
    const float* __restrict__ b_d3, const float* __restrict__ b_o1,
    const float* __restrict__ b_o2, const float* __restrict__ b_o3)
{
    const int t = threadIdx.x;
    if (t < 256) g_pack.w2p[t] = pack2(w_d2[t], w_o2[t]);
    if (t < 32)  g_pack.w1p[t] = pack2(w_d1[t], w_o1[t]);
    if (t < 16)  {
        g_pack.b1p[t]   = pack2(b_d1[t], b_o1[t]);
        g_pack.b2p[t]   = pack2(b_d2[t], b_o2[t]);
        g_pack.wd3ap[t] = pack2(w_d3[t * 2 + 0], w_d3[t * 2 + 0]);
        g_pack.wd3bp[t] = pack2(w_d3[t * 2 + 1], w_d3[t * 2 + 1]);
        g_pack.wo3p[t]  = pack2(w_o3[t], w_o3[t]);
    }
    if (t == 0) {
        g_pack.bd30p = pack2(b_d3[0], b_d3[0]);
        g_pack.bd31p = pack2(b_d3[1], b_d3[1]);
        g_pack.bo3p  = pack2(b_o3[0], b_o3[0]);
    }
}

struct Carry { ull d30p, d31p, cp; };

// One mainloop k-iteration for pair N (layer-1 activation + layer-2 j-sweep).
__device__ __forceinline__ void ml_iter(int k,
    ull x0A, ull x1A, ull x0B, ull x1B, ull* accA, ull* accB)
{
    const ull w1k0 = c_p.w1p[k];
    const ull w1k1 = c_p.w1p[16 + k];
    const ull b1k  = c_p.b1p[k];
    const ull hA = tanh2(fma2(x0A, w1k0, fma2(x1A, w1k1, b1k)));
    const ull hB = tanh2(fma2(x0B, w1k0, fma2(x1B, w1k1, b1k)));
    #pragma unroll
    for (int j2 = 0; j2 < 8; j2++) {
        const ulonglong2 w =
            *reinterpret_cast<const ulonglong2*>(&c_p.w2p[k * 16 + j2 * 2]);
        accA[j2 * 2 + 0] = fma2(hA, w.x, accA[j2 * 2 + 0]);
        accA[j2 * 2 + 1] = fma2(hA, w.y, accA[j2 * 2 + 1]);
        accB[j2 * 2 + 0] = fma2(hB, w.x, accB[j2 * 2 + 0]);
        accB[j2 * 2 + 1] = fma2(hB, w.y, accB[j2 * 2 + 1]);
    }
}

// One layer-3 k-iteration for pair C (MUFU-heavy).
__device__ __forceinline__ void l3_iter(int k, ull aAk, ull aBk, Carry& cy)
{
    float pdA, poA; unpack2(aAk, pdA, poA);
    float pdB, poB; unpack2(aBk, pdB, poB);
    const ull gdp = pack2(tanh_ap(pdA), tanh_ap(pdB));
    const ull gop = pack2(tanh_ap(poA), tanh_ap(poB));
    cy.d30p = fma2(gdp, c_p.wd3ap[k], cy.d30p);
    cy.d31p = fma2(gdp, c_p.wd3bp[k], cy.d31p);
    cy.cp   = fma2(gop, c_p.wo3p[k],  cy.cp);
}

__device__ __forceinline__ void acc_init(ull* accA, ull* accB) {
    #pragma unroll
    for (int j = 0; j < 16; j++) { accA[j] = c_p.b2p[j]; accB[j] = accA[j]; }
}
__device__ __forceinline__ Carry carry_init() {
    Carry cy; cy.d30p = c_p.bd30p; cy.d31p = c_p.bd31p; cy.cp = c_p.bo3p;
    return cy;
}

// Epilogue for pair C: carries + its x -> output float4.
__device__ __forceinline__ float4 epilogue(const float4 xi, const Carry& cy)
{
    float d30A, d30B, d31A, d31B;
    unpack2(cy.d30p, d30A, d30B);
    unpack2(cy.d31p, d31A, d31B);
    const ull x0p = pack2(xi.x, xi.z);
    const ull x1p = pack2(xi.y, xi.w);
    const ull k001 = pack2(0.001f, 0.001f);
    const ull r0 = pack2(fmaxf(d30A, 0.0f), fmaxf(d30B, 0.0f));
    const ull r1 = pack2(fmaxf(d31A, 0.0f), fmaxf(d31B, 0.0f));
    const ull ap = mul2(add2(r0, k001), x0p);
    const ull bp = mul2(add2(r1, k001), x1p);
    const ull acp  = mul2(ap, cy.cp);
    const ull aap  = mul2(ap, ap);
    const ull ccbb = fma2(cy.cp, cy.cp, mul2(bp, bp));
    const ull D0p  = fma2(aap, x0p, mul2(acp, x1p));
    const ull D1p  = fma2(acp, x0p, mul2(ccbb, x1p));
    float D0A, D0B, D1A, D1B;
    unpack2(D0p, D0A, D0B);
    unpack2(D1p, D1A, D1B);
    return make_float4(D0A, D1A, D0B, D1B);
}

__global__ __launch_bounds__(NT, 3) void damping_kernel(
    const float4* __restrict__ x, float4* __restrict__ out, int npairs)
{
    const int tid    = blockIdx.x * NT + threadIdx.x;
    const int stride = gridDim.x * NT;

    // 4 pairs per thread (index-clamped; duplicate writes carry equal values).
    int p0 = tid;                 if (p0 >= npairs) p0 = npairs - 1;
    int p1 = tid + stride;        if (p1 >= npairs) p1 = npairs - 1;
    int p2 = tid + 2 * stride;    if (p2 >= npairs) p2 = npairs - 1;
    int p3 = tid + 3 * stride;    if (p3 >= npairs) p3 = npairs - 1;

    const float4 xi0 = x[p0];
    const float4 xi1 = x[p1];
    const float4 xi2 = x[p2];
    const float4 xi3 = x[p3];

    ull a0A[16], a0B[16], a1A[16], a1B[16];
    Carry cy;

    // ---- stage 0: mainloop(pair0) alone (prologue) ----
    {
        const ull x0A = pack2(xi0.x, xi0.x), x1A = pack2(xi0.y, xi0.y);
        const ull x0B = pack2(xi0.z, xi0.z), x1B = pack2(xi0.w, xi0.w);
        acc_init(a0A, a0B);
        #pragma unroll
        for (int k = 0; k < 16; k++) ml_iter(k, x0A, x1A, x0B, x1B, a0A, a0B);
    }

    // ---- stage 1: ML(pair1) fused with L3(pair0) ----
    {
        const ull x0A = pack2(xi1.x, xi1.x), x1A = pack2(xi1.y, xi1.y);
        const ull x0B = pack2(xi1.z, xi1.z), x1B = pack2(xi1.w, xi1.w);
        acc_init(a1A, a1B);
        cy = carry_init();
        #pragma unroll
        for (int k = 0; k < 16; k++) {
            ml_iter(k, x0A, x1A, x0B, x1B, a1A, a1B);
            l3_iter(k, a0A[k], a0B[k], cy);
        }
        out[p0] = epilogue(xi0, cy);
    }

    // ---- stage 2: ML(pair2) fused with L3(pair1) ----
    {
        const ull x0A = pack2(xi2.x, xi2.x), x1A = pack2(xi2.y, xi2.y);
        const ull x0B = pack2(xi2.z, xi2.z), x1B = pack2(xi2.w, xi2.w);
        acc_init(a0A, a0B);
        cy = carry_init();
        #pragma unroll
        for (int k = 0; k < 16; k++) {
            ml_iter(k, x0A, x1A, x0B, x1B, a0A, a0B);
            l3_iter(k, a1A[k], a1B[k], cy);
        }
        out[p1] = epilogue(xi1, cy);
    }

    // ---- stage 3: ML(pair3) fused with L3(pair2) ----
    {
        const ull x0A = pack2(xi3.x, xi3.x), x1A = pack2(xi3.y, xi3.y);
        const ull x0B = pack2(xi3.z, xi3.z), x1B = pack2(xi3.w, xi3.w);
        acc_init(a1A, a1B);
        cy = carry_init();
        #pragma unroll
        for (int k = 0; k < 16; k++) {
            ml_iter(k, x0A, x1A, x0B, x1B, a1A, a1B);
            l3_iter(k, a0A[k], a0B[k], cy);
        }
        out[p2] = epilogue(xi2, cy);
    }

    // ---- stage 4: L3(pair3) alone (drain) ----
    {
        cy = carry_init();
        #pragma unroll
        for (int k = 0; k < 16; k++) l3_iter(k, a1A[k], a1B[k], cy);
        out[p3] = epilogue(xi3, cy);
    }
}

extern "C" void kernel_launch(void* const* d_in, const int* in_sizes, int n_in,
                              void* d_out, int out_size) {
    const float4* x   = (const float4*)d_in[0];
    const float* w_d1 = (const float*)d_in[1];
    const float* w_d2 = (const float*)d_in[2];
    const float* w_d3 = (const float*)d_in[3];
    const float* w_o1 = (const float*)d_in[4];
    const float* w_o2 = (const float*)d_in[5];
    const float* w_o3 = (const float*)d_in[6];
    const float* b_d1 = (const float*)d_in[7];
    const float* b_d2 = (const float*)d_in[8];
    const float* b_d3 = (const float*)d_in[9];
    const float* b_o1 = (const float*)d_in[10];
    const float* b_o2 = (const float*)d_in[11];
    const float* b_o3 = (const float*)d_in[12];
    float4* out = (float4*)d_out;

    pack_kernel<<<1, 256>>>(w_d1, w_d2, w_d3, w_o1, w_o2, w_o3,
                            b_d1, b_d2, b_d3, b_o1, b_o2, b_o3);

    void* src = nullptr;
    cudaGetSymbolAddress(&src, g_pack);
    cudaMemcpyToSymbolAsync(c_p, src, sizeof(Params), 0,
                            cudaMemcpyDeviceToDevice, 0);

    const int nrows  = in_sizes[0] / 2;
    const int npairs = nrows / 2;                       // 2,097,152
    const int grid   = (npairs + ITERS * NT - 1) / (ITERS * NT);  // 4096
    damping_kernel<<<grid, NT>>>(x, out, npairs);
}